// round 11
// baseline (speedup 1.0000x reference)
#include <cuda_runtime.h>
#include <cuda_fp16.h>
#include <cstdint>
#include <math.h>

#define DD 768
#define MM 8192
#define CC 2048
#define LL 16

#define BM 128
#define BN 128
#define BK 32
#define NITER (DD / BK)       // 24
#define NSTAGE 4

// padded smem row: 32 data + 8 pad fp16 = 80B (conflict-free ldmatrix)
#define LDT 40
#define OFF_A 0
#define OFF_B (BM * LDT * 2)                 // 10240
#define STAGE_BYTES (OFF_B + BN * LDT * 2)   // 20480
#define SMEM_TOTAL (NSTAGE * STAGE_BYTES)    // 81920

// ---------------- device globals ----------------
__device__ float g_s[MM];
__device__ __half g_Xh[MM * DD];
__device__ __half g_Bh[DD * DD];   // [n][k] = W1[k][n] (transposed, K-major)

// ---------------- helpers ----------------
__device__ __forceinline__ uint32_t smem_u32(const void* p) {
    uint32_t a;
    asm("{ .reg .u64 t; cvta.to.shared.u64 t, %1; cvt.u32.u64 %0, t; }" : "=r"(a) : "l"(p));
    return a;
}
__device__ __forceinline__ void cp16(uint32_t dst, const void* src) {
    asm volatile("cp.async.cg.shared.global [%0], [%1], 16;" :: "r"(dst), "l"(src));
}
__device__ __forceinline__ void ldsm4(uint32_t* r, uint32_t addr) {
    asm volatile("ldmatrix.sync.aligned.m8n8.x4.shared.b16 {%0,%1,%2,%3}, [%4];"
                 : "=r"(r[0]), "=r"(r[1]), "=r"(r[2]), "=r"(r[3]) : "r"(addr));
}
__device__ __forceinline__ void mma16816(float* c, const uint32_t* a, const uint32_t* b) {
    asm volatile(
        "mma.sync.aligned.m16n8k16.row.col.f32.f16.f16.f32 "
        "{%0,%1,%2,%3}, {%4,%5,%6,%7}, {%8,%9}, {%0,%1,%2,%3};"
        : "+f"(c[0]), "+f"(c[1]), "+f"(c[2]), "+f"(c[3])
        : "r"(a[0]), "r"(a[1]), "r"(a[2]), "r"(a[3]), "r"(b[0]), "r"(b[1]));
}

// ---------------- fused precompute (X convert + zero_s + W1 transpose convert) ----
#define NXBLK (MM * DD / 4 / 256)   // 6144 X-blocks; then 576 W1-blocks

__global__ void convert_all_kernel(const float* __restrict__ X,
                                   const float* __restrict__ W1) {
    int b = blockIdx.x;
    int tid = threadIdx.x;
    if (b < NXBLK) {
        int i = b * 256 + tid;
        if (i < MM) g_s[i] = 0.0f;
        float4 v = ((const float4*)X)[i];
        __half h0 = __float2half_rn(v.x), h1 = __float2half_rn(v.y);
        __half h2 = __float2half_rn(v.z), h3 = __float2half_rn(v.w);
        uint2 ph;
        ph.x = ((uint32_t)*(uint16_t*)&h1 << 16) | *(uint16_t*)&h0;
        ph.y = ((uint32_t)*(uint16_t*)&h3 << 16) | *(uint16_t*)&h2;
        ((uint2*)g_Xh)[i] = ph;
    } else {
        __shared__ float t[32][33];
        int bb = b - NXBLK;                       // 0..575
        int n0 = (bb % (DD / 32)) * 32;
        int k0 = (bb / (DD / 32)) * 32;
        int tx = tid & 31, ty = tid >> 5;         // (32, 8)
#pragma unroll
        for (int i = 0; i < 32; i += 8)
            t[ty + i][tx] = W1[(size_t)(k0 + ty + i) * DD + n0 + tx];
        __syncthreads();
#pragma unroll
        for (int i = 0; i < 32; i += 8)
            g_Bh[(size_t)(n0 + ty + i) * DD + k0 + tx] = __float2half_rn(t[tx][ty + i]);
    }
}

// ---------------- mma.sync score GEMM: 4 warps x (64x64) warp tiles ----------------
__device__ __forceinline__ void load_stage(uint32_t base, int k0, int m0, int n0, int tid) {
    int r = tid >> 2;                 // 0..31
    int cb = tid & 3;                 // 16B block (8 fp16) within 64B row
#pragma unroll
    for (int p = 0; p < 4; p++) {     // A: 128 rows
        int row = p * 32 + r;
        uint32_t so = (uint32_t)row * (LDT * 2) + cb * 16;
        cp16(base + OFF_A + so, g_Xh + (size_t)(m0 + row) * DD + k0 + cb * 8);
    }
#pragma unroll
    for (int p = 0; p < 4; p++) {     // B: 128 rows
        int row = p * 32 + r;
        uint32_t so = (uint32_t)row * (LDT * 2) + cb * 16;
        cp16(base + OFF_B + so, g_Bh + (size_t)(n0 + row) * DD + k0 + cb * 8);
    }
    asm volatile("cp.async.commit_group;" ::: "memory");
}

__global__ __launch_bounds__(128, 2) void score_gemm_mma(
    const float* __restrict__ b1, const float* __restrict__ Wout) {
    extern __shared__ char smem[];
    uint32_t sb = smem_u32(smem);
    const int tid = threadIdx.x;
    const int wid = tid >> 5, lane = tid & 31;
    const int wm = (wid >> 1) * 64;           // warp m offset (0/64)
    const int wn = (wid & 1) * 64;            // warp n offset (0/64)
    const int m0 = blockIdx.y * BM, n0 = blockIdx.x * BN;

    float acc[4][8][4];
#pragma unroll
    for (int mt = 0; mt < 4; mt++)
#pragma unroll
        for (int nt = 0; nt < 8; nt++)
#pragma unroll
            for (int c = 0; c < 4; c++) acc[mt][nt][c] = 0.0f;

    // prologue: 3 stages in flight
    load_stage(sb, 0, m0, n0, tid);
    load_stage(sb + STAGE_BYTES, BK, m0, n0, tid);
    load_stage(sb + 2 * STAGE_BYTES, 2 * BK, m0, n0, tid);

    // ldmatrix lane offsets
    const uint32_t aRow = (lane & 15);
    const uint32_t aCol = (lane >> 4) << 3;
    const uint32_t bN   = ((lane >> 4) << 3) + (lane & 7);
    const uint32_t bK   = ((lane >> 3) & 1) << 3;

    for (int it = 0; it < NITER; it++) {
        // pending groups newer than `it` = min(3, NITER-1-it)
        if (it < NITER - 3)       asm volatile("cp.async.wait_group 3;" ::: "memory");
        else if (it == NITER - 3) asm volatile("cp.async.wait_group 2;" ::: "memory");
        else if (it == NITER - 2) asm volatile("cp.async.wait_group 1;" ::: "memory");
        else                      asm volatile("cp.async.wait_group 0;" ::: "memory");
        __syncthreads();
        uint32_t st = sb + (it % NSTAGE) * STAGE_BYTES;
        if (it + 3 < NITER)
            load_stage(sb + ((it + 3) % NSTAGE) * STAGE_BYTES, (it + 3) * BK, m0, n0, tid);

        // per k16 half: 8 ldsm feed 32 MMAs (4:1 MMA:LDSM)
#pragma unroll
        for (int h = 0; h < 2; h++) {
            int kk = h * 16;
            uint32_t Ah[4][4], Bh[4][4];
#pragma unroll
            for (int mt = 0; mt < 4; mt++) {
                uint32_t off = ((wm + mt * 16 + aRow) * LDT + kk + aCol) * 2;
                ldsm4(Ah[mt], st + OFF_A + off);
            }
#pragma unroll
            for (int np = 0; np < 4; np++) {
                uint32_t off = ((wn + np * 16 + bN) * LDT + kk + bK) * 2;
                ldsm4(Bh[np], st + OFF_B + off);
            }
#pragma unroll
            for (int mt = 0; mt < 4; mt++)
#pragma unroll
                for (int np = 0; np < 4; np++) {
                    mma16816(acc[mt][2 * np],     Ah[mt], Bh[np]);
                    mma16816(acc[mt][2 * np + 1], Ah[mt], Bh[np] + 2);
                }
        }
    }

    // epilogue: bias + relu + dot(Wout), quad-reduce, atomic per-mention score
    const int qr = lane >> 2;
    const int qc = lane & 3;
#pragma unroll
    for (int mt = 0; mt < 4; mt++) {
        float r0 = 0.0f, r1 = 0.0f;
#pragma unroll
        for (int nt = 0; nt < 8; nt++) {
            int n = n0 + wn + nt * 8 + qc * 2;
            float w0 = Wout[n], w1 = Wout[n + 1];
            float bb0 = b1[n], bb1 = b1[n + 1];
            r0 += fmaxf(acc[mt][nt][0] + bb0, 0.0f) * w0 +
                  fmaxf(acc[mt][nt][1] + bb1, 0.0f) * w1;
            r1 += fmaxf(acc[mt][nt][2] + bb0, 0.0f) * w0 +
                  fmaxf(acc[mt][nt][3] + bb1, 0.0f) * w1;
        }
        r0 += __shfl_xor_sync(0xffffffffu, r0, 1);
        r0 += __shfl_xor_sync(0xffffffffu, r0, 2);
        r1 += __shfl_xor_sync(0xffffffffu, r1, 1);
        r1 += __shfl_xor_sync(0xffffffffu, r1, 2);
        if (qc == 0) {
            atomicAdd(&g_s[m0 + wm + mt * 16 + qr], r0);
            atomicAdd(&g_s[m0 + wm + mt * 16 + qr + 8], r1);
        }
    }
}

// ---------------- softmax + aggregation: no smem, no syncthreads ----------------
__global__ __launch_bounds__(192) void softmax_agg_kernel(
    const float* __restrict__ X, const int* __restrict__ cidx,
    const int* __restrict__ clen, float* __restrict__ out) {
    const int c = blockIdx.x;
    const int tid = threadIdx.x;
    const int len = clen[c];

    int ix[LL];
    const int4* cp = (const int4*)(cidx + c * LL);
#pragma unroll
    for (int q = 0; q < 4; q++) {
        int4 v = cp[q];
        ix[4 * q + 0] = v.x; ix[4 * q + 1] = v.y;
        ix[4 * q + 2] = v.z; ix[4 * q + 3] = v.w;
    }
    float sc[LL];
#pragma unroll
    for (int l = 0; l < LL; l++)
        sc[l] = (l < len) ? g_s[ix[l]] : -INFINITY;

    float mx = -INFINITY;
#pragma unroll
    for (int l = 0; l < LL; l++) mx = fmaxf(mx, sc[l]);
    float p[LL];
    float sum = 0.0f;
#pragma unroll
    for (int l = 0; l < LL; l++) { p[l] = __expf(sc[l] - mx); sum += p[l]; }
    float inv = 1.0f / sum;
#pragma unroll
    for (int l = 0; l < LL; l++) p[l] *= inv;

    const float4* Xv = (const float4*)X;      // row stride DD/4 = 192
    float4 a = make_float4(0.f, 0.f, 0.f, 0.f);
#pragma unroll
    for (int l = 0; l < LL; l++) {
        float4 v = Xv[(size_t)ix[l] * (DD / 4) + tid];
        a.x += p[l] * v.x; a.y += p[l] * v.y;
        a.z += p[l] * v.z; a.w += p[l] * v.w;
    }
    ((float4*)out)[(size_t)c * (DD / 4) + tid] = a;
}

extern "C" void kernel_launch(void* const* d_in, const int* in_sizes, int n_in,
                              void* d_out, int out_size) {
    const float* X    = (const float*)d_in[0];
    const int*   cidx = (const int*)d_in[1];
    const int*   clen = (const int*)d_in[2];
    const float* W1   = (const float*)d_in[3];
    const float* b1   = (const float*)d_in[4];
    const float* Wout = (const float*)d_in[5];
    float* out = (float*)d_out;

    cudaFuncSetAttribute(score_gemm_mma, cudaFuncAttributeMaxDynamicSharedMemorySize,
                         SMEM_TOTAL);

    convert_all_kernel<<<NXBLK + (DD / 32) * (DD / 32), 256>>>(X, W1);
    score_gemm_mma<<<dim3(DD / BN, MM / BM), 128, SMEM_TOTAL>>>(b1, Wout);
    softmax_agg_kernel<<<CC, 192>>>(X, cidx, clen, out);
}

// round 12
// speedup vs baseline: 1.0322x; 1.0322x over previous
#include <cuda_runtime.h>
#include <cuda_fp16.h>
#include <cstdint>
#include <math.h>

#define DD 768
#define MM 8192
#define CC 2048
#define LL 16

#define BM 64
#define BN 128
#define BK 32
#define NITER (DD / BK)       // 24
#define NSTAGE 4

// padded smem row: 32 data + 8 pad fp16 = 80B (conflict-free ldmatrix)
#define LDT 40
#define OFF_A 0
#define OFF_B (BM * LDT * 2)                 // 5120
#define STAGE_BYTES (OFF_B + BN * LDT * 2)   // 15360
#define SMEM_TOTAL (NSTAGE * STAGE_BYTES)    // 61440

// ---------------- device globals ----------------
__device__ float g_s[MM];
__device__ __half g_Xh[MM * DD];
__device__ __half g_Bh[DD * DD];   // [n][k] = W1[k][n] (transposed, K-major)

// ---------------- helpers ----------------
__device__ __forceinline__ uint32_t smem_u32(const void* p) {
    uint32_t a;
    asm("{ .reg .u64 t; cvta.to.shared.u64 t, %1; cvt.u32.u64 %0, t; }" : "=r"(a) : "l"(p));
    return a;
}
__device__ __forceinline__ void cp16(uint32_t dst, const void* src) {
    asm volatile("cp.async.cg.shared.global [%0], [%1], 16;" :: "r"(dst), "l"(src));
}
__device__ __forceinline__ void ldsm4(uint32_t* r, uint32_t addr) {
    asm volatile("ldmatrix.sync.aligned.m8n8.x4.shared.b16 {%0,%1,%2,%3}, [%4];"
                 : "=r"(r[0]), "=r"(r[1]), "=r"(r[2]), "=r"(r[3]) : "r"(addr));
}
__device__ __forceinline__ void mma16816(float* c, const uint32_t* a, const uint32_t* b) {
    asm volatile(
        "mma.sync.aligned.m16n8k16.row.col.f32.f16.f16.f32 "
        "{%0,%1,%2,%3}, {%4,%5,%6,%7}, {%8,%9}, {%0,%1,%2,%3};"
        : "+f"(c[0]), "+f"(c[1]), "+f"(c[2]), "+f"(c[3])
        : "r"(a[0]), "r"(a[1]), "r"(a[2]), "r"(a[3]), "r"(b[0]), "r"(b[1]));
}

// ---------------- fused precompute, MLP=4 on the X pass ----------------
#define NXBLK (MM * DD / 4 / 1024)   // 1536 X-blocks (4 float4 per thread); then 576 W1-blocks

__global__ void convert_all_kernel(const float* __restrict__ X,
                                   const float* __restrict__ W1) {
    int b = blockIdx.x;
    int tid = threadIdx.x;
    if (b < NXBLK) {
        int i0 = b * 1024 + tid;
        float4 v[4];
#pragma unroll
        for (int k = 0; k < 4; k++) v[k] = ((const float4*)X)[i0 + k * 256];
#pragma unroll
        for (int k = 0; k < 4; k++) {
            int i = i0 + k * 256;
            if (i < MM) g_s[i] = 0.0f;
            __half h0 = __float2half_rn(v[k].x), h1 = __float2half_rn(v[k].y);
            __half h2 = __float2half_rn(v[k].z), h3 = __float2half_rn(v[k].w);
            uint2 ph;
            ph.x = ((uint32_t)*(uint16_t*)&h1 << 16) | *(uint16_t*)&h0;
            ph.y = ((uint32_t)*(uint16_t*)&h3 << 16) | *(uint16_t*)&h2;
            ((uint2*)g_Xh)[i] = ph;
        }
    } else {
        __shared__ float t[32][33];
        int bb = b - NXBLK;                       // 0..575
        int n0 = (bb % (DD / 32)) * 32;
        int k0 = (bb / (DD / 32)) * 32;
        int tx = tid & 31, ty = tid >> 5;         // (32, 8)
#pragma unroll
        for (int i = 0; i < 32; i += 8)
            t[ty + i][tx] = W1[(size_t)(k0 + ty + i) * DD + n0 + tx];
        __syncthreads();
#pragma unroll
        for (int i = 0; i < 32; i += 8)
            g_Bh[(size_t)(n0 + ty + i) * DD + k0 + tx] = __float2half_rn(t[tx][ty + i]);
    }
}

// ---------------- mma.sync score GEMM (frozen R7 config, ~35us known-good) -------
__device__ __forceinline__ void load_stage(uint32_t base, int k0, int m0, int n0, int tid) {
    int r = tid >> 2;                 // 0..31
    int cb = tid & 3;                 // 16B block (8 fp16) within 64B row
#pragma unroll
    for (int p = 0; p < 2; p++) {     // A: 64 rows
        int row = p * 32 + r;
        uint32_t so = (uint32_t)row * (LDT * 2) + cb * 16;
        cp16(base + OFF_A + so, g_Xh + (size_t)(m0 + row) * DD + k0 + cb * 8);
    }
#pragma unroll
    for (int p = 0; p < 4; p++) {     // B: 128 rows
        int row = p * 32 + r;
        uint32_t so = (uint32_t)row * (LDT * 2) + cb * 16;
        cp16(base + OFF_B + so, g_Bh + (size_t)(n0 + row) * DD + k0 + cb * 8);
    }
    asm volatile("cp.async.commit_group;" ::: "memory");
}

__global__ __launch_bounds__(128, 3) void score_gemm_mma(
    const float* __restrict__ b1, const float* __restrict__ Wout) {
    extern __shared__ char smem[];
    uint32_t sb = smem_u32(smem);
    const int tid = threadIdx.x;
    const int wid = tid >> 5, lane = tid & 31;
    const int wm = (wid >> 1) * 32;           // warp m offset (0/32)
    const int wn = (wid & 1) * 64;            // warp n offset (0/64)
    const int m0 = blockIdx.y * BM, n0 = blockIdx.x * BN;

    float acc[2][8][4];
#pragma unroll
    for (int mt = 0; mt < 2; mt++)
#pragma unroll
        for (int nt = 0; nt < 8; nt++)
#pragma unroll
            for (int c = 0; c < 4; c++) acc[mt][nt][c] = 0.0f;

    // prologue: 3 stages in flight
    load_stage(sb, 0, m0, n0, tid);
    load_stage(sb + STAGE_BYTES, BK, m0, n0, tid);
    load_stage(sb + 2 * STAGE_BYTES, 2 * BK, m0, n0, tid);

    // ldmatrix lane offsets
    const uint32_t aRow = (lane & 15);
    const uint32_t aCol = (lane >> 4) << 3;
    const uint32_t bN   = ((lane >> 4) << 3) + (lane & 7);
    const uint32_t bK   = ((lane >> 3) & 1) << 3;

    for (int it = 0; it < NITER; it++) {
        // exact drain: stages newer than `it` still loading = min(2, NITER-1-it)
        if (it < NITER - 2)       asm volatile("cp.async.wait_group 2;" ::: "memory");
        else if (it == NITER - 2) asm volatile("cp.async.wait_group 1;" ::: "memory");
        else                      asm volatile("cp.async.wait_group 0;" ::: "memory");
        __syncthreads();
        uint32_t st = sb + (it % NSTAGE) * STAGE_BYTES;
        if (it + 3 < NITER)
            load_stage(sb + ((it + 3) % NSTAGE) * STAGE_BYTES, (it + 3) * BK, m0, n0, tid);

        // load all frags for this BK=32 iter, then 32 back-to-back MMAs
        uint32_t Ah[2][2][4], Bh[2][4][4];
#pragma unroll
        for (int h = 0; h < 2; h++) {
            int kk = h * 16;
#pragma unroll
            for (int mt = 0; mt < 2; mt++) {
                uint32_t off = ((wm + mt * 16 + aRow) * LDT + kk + aCol) * 2;
                ldsm4(Ah[h][mt], st + OFF_A + off);
            }
#pragma unroll
            for (int np = 0; np < 4; np++) {
                uint32_t off = ((wn + np * 16 + bN) * LDT + kk + bK) * 2;
                ldsm4(Bh[h][np], st + OFF_B + off);
            }
        }
#pragma unroll
        for (int h = 0; h < 2; h++)
#pragma unroll
            for (int mt = 0; mt < 2; mt++)
#pragma unroll
                for (int np = 0; np < 4; np++) {
                    mma16816(acc[mt][2 * np],     Ah[h][mt], Bh[h][np]);
                    mma16816(acc[mt][2 * np + 1], Ah[h][mt], Bh[h][np] + 2);
                }
    }

    // epilogue: bias + relu + dot(Wout), quad-reduce, atomic per-mention score
    const int qr = lane >> 2;
    const int qc = lane & 3;
#pragma unroll
    for (int mt = 0; mt < 2; mt++) {
        float r0 = 0.0f, r1 = 0.0f;
#pragma unroll
        for (int nt = 0; nt < 8; nt++) {
            int n = n0 + wn + nt * 8 + qc * 2;
            float w0 = Wout[n], w1 = Wout[n + 1];
            float bb0 = b1[n], bb1 = b1[n + 1];
            r0 += fmaxf(acc[mt][nt][0] + bb0, 0.0f) * w0 +
                  fmaxf(acc[mt][nt][1] + bb1, 0.0f) * w1;
            r1 += fmaxf(acc[mt][nt][2] + bb0, 0.0f) * w0 +
                  fmaxf(acc[mt][nt][3] + bb1, 0.0f) * w1;
        }
        r0 += __shfl_xor_sync(0xffffffffu, r0, 1);
        r0 += __shfl_xor_sync(0xffffffffu, r0, 2);
        r1 += __shfl_xor_sync(0xffffffffu, r1, 1);
        r1 += __shfl_xor_sync(0xffffffffu, r1, 2);
        if (qc == 0) {
            atomicAdd(&g_s[m0 + wm + mt * 16 + qr], r0);
            atomicAdd(&g_s[m0 + wm + mt * 16 + qr + 8], r1);
        }
    }
}

// ---------------- softmax + aggregation: 2 concepts per 384-thread block ---------
__global__ __launch_bounds__(384) void softmax_agg_kernel(
    const float* __restrict__ X, const int* __restrict__ cidx,
    const int* __restrict__ clen, float* __restrict__ out) {
    const int half = threadIdx.x / 192;              // 0 or 1
    const int tid = threadIdx.x % 192;
    const int c = blockIdx.x * 2 + half;
    const int len = clen[c];

    int ix[LL];
    const int4* cp = (const int4*)(cidx + c * LL);
#pragma unroll
    for (int q = 0; q < 4; q++) {
        int4 v = cp[q];
        ix[4 * q + 0] = v.x; ix[4 * q + 1] = v.y;
        ix[4 * q + 2] = v.z; ix[4 * q + 3] = v.w;
    }
    float sc[LL];
#pragma unroll
    for (int l = 0; l < LL; l++)
        sc[l] = (l < len) ? g_s[ix[l]] : -INFINITY;

    float mx = -INFINITY;
#pragma unroll
    for (int l = 0; l < LL; l++) mx = fmaxf(mx, sc[l]);
    float p[LL];
    float sum = 0.0f;
#pragma unroll
    for (int l = 0; l < LL; l++) { p[l] = __expf(sc[l] - mx); sum += p[l]; }
    float inv = 1.0f / sum;
#pragma unroll
    for (int l = 0; l < LL; l++) p[l] *= inv;

    const float4* Xv = (const float4*)X;      // row stride DD/4 = 192
    float4 a = make_float4(0.f, 0.f, 0.f, 0.f);
#pragma unroll
    for (int l = 0; l < LL; l++) {
        float4 v = Xv[(size_t)ix[l] * (DD / 4) + tid];
        a.x += p[l] * v.x; a.y += p[l] * v.y;
        a.z += p[l] * v.z; a.w += p[l] * v.w;
    }
    ((float4*)out)[(size_t)c * (DD / 4) + tid] = a;
}

extern "C" void kernel_launch(void* const* d_in, const int* in_sizes, int n_in,
                              void* d_out, int out_size) {
    const float* X    = (const float*)d_in[0];
    const int*   cidx = (const int*)d_in[1];
    const int*   clen = (const int*)d_in[2];
    const float* W1   = (const float*)d_in[3];
    const float* b1   = (const float*)d_in[4];
    const float* Wout = (const float*)d_in[5];
    float* out = (float*)d_out;

    cudaFuncSetAttribute(score_gemm_mma, cudaFuncAttributeMaxDynamicSharedMemorySize,
                         SMEM_TOTAL);

    convert_all_kernel<<<NXBLK + (DD / 32) * (DD / 32), 256>>>(X, W1);
    score_gemm_mma<<<dim3(DD / BN, MM / BM), 128, SMEM_TOTAL>>>(b1, Wout);
    softmax_agg_kernel<<<CC / 2, 384>>>(X, cidx, clen, out);
}